// round 2
// baseline (speedup 1.0000x reference)
#include <cuda_runtime.h>
#include <cstddef>

#define H 384
#define W 384
#define BATCH 2
#define TX 16
#define TY 8
#define NT (TX*TY)
#define NWIN 48

// ---------------- scratch (no cudaMalloc allowed) ----------------
__device__ float g_h1[(size_t)BATCH*64*H*W];    // branch conv1 output
__device__ float g_h2[(size_t)BATCH*32*H*W];    // branch conv2 output
__device__ float g_feat[(size_t)BATCH*H*W*96];  // channel-last q|k|v
__device__ float g_aout[(size_t)BATCH*32*H*W];  // attention output (shifted space, NCHW)

// ---------------- generic direct 3x3 conv, SAME padding ----------------
// grid (W/TX, H/TY, BATCH), block NT threads. Each thread: one pixel, all COUT.
template<int CIN, int COUT, int CHUNK, bool RELU, bool CHLAST>
__global__ __launch_bounds__(NT)
void conv3x3_k(const float* __restrict__ in, const float* __restrict__ wt,
               const float* __restrict__ bias, float* __restrict__ out, int coutOff)
{
    __shared__ float sIn[CHUNK][TY+2][TX+2];
    __shared__ float sW[COUT][CHUNK][9];

    const int bx = blockIdx.x * TX, by = blockIdx.y * TY, bb = blockIdx.z;
    const int tid = threadIdx.x;
    const int lx = tid % TX, ly = tid / TX;

    float acc[COUT];
    #pragma unroll
    for (int co = 0; co < COUT; co++) acc[co] = __ldg(&bias[co]);

    for (int c0 = 0; c0 < CIN; c0 += CHUNK) {
        __syncthreads();
        // weights chunk -> smem
        for (int idx = tid; idx < COUT*CHUNK*9; idx += NT) {
            int co = idx / (CHUNK*9);
            int r  = idx - co*(CHUNK*9);
            int ci = r / 9;
            int t  = r - ci*9;
            sW[co][ci][t] = wt[(co*CIN + c0 + ci)*9 + t];
        }
        // input tile + halo -> smem (zero padded)
        for (int idx = tid; idx < CHUNK*(TY+2)*(TX+2); idx += NT) {
            int ci = idx / ((TY+2)*(TX+2));
            int r  = idx - ci*((TY+2)*(TX+2));
            int yy = r / (TX+2);
            int xx = r - yy*(TX+2);
            int gy = by + yy - 1, gx = bx + xx - 1;
            float v = 0.f;
            if ((unsigned)gy < (unsigned)H && (unsigned)gx < (unsigned)W)
                v = in[((bb*CIN + c0 + ci)*H + gy)*W + gx];
            sIn[ci][yy][xx] = v;
        }
        __syncthreads();

        #pragma unroll 2
        for (int ci = 0; ci < CHUNK; ci++) {
            float r00 = sIn[ci][ly+0][lx+0], r01 = sIn[ci][ly+0][lx+1], r02 = sIn[ci][ly+0][lx+2];
            float r10 = sIn[ci][ly+1][lx+0], r11 = sIn[ci][ly+1][lx+1], r12 = sIn[ci][ly+1][lx+2];
            float r20 = sIn[ci][ly+2][lx+0], r21 = sIn[ci][ly+2][lx+1], r22 = sIn[ci][ly+2][lx+2];
            #pragma unroll
            for (int co = 0; co < COUT; co++) {
                const float* wp = &sW[co][ci][0];
                float a = acc[co];
                a = fmaf(r00, wp[0], a);
                a = fmaf(r01, wp[1], a);
                a = fmaf(r02, wp[2], a);
                a = fmaf(r10, wp[3], a);
                a = fmaf(r11, wp[4], a);
                a = fmaf(r12, wp[5], a);
                a = fmaf(r20, wp[6], a);
                a = fmaf(r21, wp[7], a);
                a = fmaf(r22, wp[8], a);
                acc[co] = a;
            }
        }
    }

    const int gy = by + ly, gx = bx + lx;
    if constexpr (CHLAST) {
        // channel-last feat: out[((b*H+y)*W+x)*96 + coutOff + co]
        float* op = out + ((size_t)(bb*H + gy)*W + gx)*96 + coutOff;
        static_assert(COUT % 4 == 0, "CHLAST requires COUT%4==0");
        #pragma unroll
        for (int co = 0; co < COUT; co += 4) {
            float4 v;
            v.x = RELU ? fmaxf(acc[co+0], 0.f) : acc[co+0];
            v.y = RELU ? fmaxf(acc[co+1], 0.f) : acc[co+1];
            v.z = RELU ? fmaxf(acc[co+2], 0.f) : acc[co+2];
            v.w = RELU ? fmaxf(acc[co+3], 0.f) : acc[co+3];
            *(float4*)(op + co) = v;
        }
    } else {
        #pragma unroll
        for (int co = 0; co < COUT; co++) {
            float v = RELU ? fmaxf(acc[co], 0.f) : acc[co];
            out[((size_t)(bb*COUT + co)*H + gy)*W + gx] = v;
        }
    }
}

// ---------------- shifted-window attention ----------------
// grid (2304, BATCH), 64 threads (one per token of an 8x8 window).
// Reads feat (channel-last) at original coords via (s+4) mod 384 -> no materialized roll.
// Writes aout in shifted space, NCHW.
__global__ __launch_bounds__(64)
void attn_k(const float* __restrict__ feat, const float* __restrict__ pos,
            float* __restrict__ aout)
{
    __shared__ float sK[64][32];
    __shared__ float sV[64][32];
    __shared__ float sPos[225];

    const int w  = blockIdx.x, bb = blockIdx.y;
    const int wh = w / NWIN, ww = w - wh*NWIN;
    const int tid = threadIdx.x;
    const int iy = tid >> 3, ix = tid & 7;
    const int sy = wh*8 + iy, sx = ww*8 + ix;
    int y = sy + 4; if (y >= H) y -= H;
    int x = sx + 4; if (x >= W) x -= W;

    // cooperative, coalesced K/V load: lanes sweep channels of one token
    for (int idx = tid; idx < 64*32; idx += 64) {
        int j = idx >> 5, c = idx & 31;
        int jy = j >> 3, jx = j & 7;
        int yy = wh*8 + jy + 4; if (yy >= H) yy -= H;
        int xx = ww*8 + jx + 4; if (xx >= W) xx -= W;
        const float* p = feat + ((size_t)(bb*H + yy)*W + xx)*96;
        sK[j][c] = p[32 + c];
        sV[j][c] = p[64 + c];
    }
    for (int idx = tid; idx < 225; idx += 64) sPos[idx] = pos[idx];

    float q[32];
    {
        const float* fp = feat + ((size_t)(bb*H + y)*W + x)*96;
        #pragma unroll
        for (int c = 0; c < 32; c += 4) {
            float4 v = *(const float4*)(fp + c);
            q[c] = v.x; q[c+1] = v.y; q[c+2] = v.z; q[c+3] = v.w;
        }
    }
    __syncthreads();

    const bool mR = (wh == NWIN-1);  // last row of windows: ul mask (y halves)
    const bool mC = (ww == NWIN-1);  // last col of windows: lr mask (x halves)
    const float scale = 0.35355339059327373f;  // 8^-0.5
    const int posOff = (7 - iy)*15 + (7 - ix);

    #pragma unroll 1
    for (int h = 0; h < 4; h++) {
        float lg[64];
        float mx = -1e30f;
        #pragma unroll
        for (int j = 0; j < 64; j++) {
            const int jy = j >> 3, jx = j & 7;
            float d = 0.f;
            #pragma unroll
            for (int dd = 0; dd < 8; dd++)
                d = fmaf(q[h*8 + dd], sK[j][h*8 + dd], d);
            float l = d*scale + sPos[jy*15 + jx + posOff];
            bool msk = (mR && ((iy >= 4) != (jy >= 4))) ||
                       (mC && ((ix >= 4) != (jx >= 4)));
            l = msk ? -1e30f : l;
            lg[j] = l;
            mx = fmaxf(mx, l);
        }
        float s = 0.f;
        #pragma unroll
        for (int j = 0; j < 64; j++) {
            float e = __expf(lg[j] - mx);
            lg[j] = e;
            s += e;
        }
        const float inv = 1.f / s;
        float oh[8];
        #pragma unroll
        for (int dd = 0; dd < 8; dd++) oh[dd] = 0.f;
        #pragma unroll
        for (int j = 0; j < 64; j++) {
            float p = lg[j];
            #pragma unroll
            for (int dd = 0; dd < 8; dd++)
                oh[dd] = fmaf(p, sV[j][h*8 + dd], oh[dd]);
        }
        #pragma unroll
        for (int dd = 0; dd < 8; dd++)
            aout[((size_t)(bb*32 + h*8 + dd)*H + sy)*W + sx] = oh[dd]*inv;
    }
}

// ---------------- output conv (32->3) + roll(+4,+4) + residual ----------------
__global__ __launch_bounds__(NT)
void conv_out_k(const float* __restrict__ in, const float* __restrict__ wt,
                const float* __restrict__ bias, const float* __restrict__ xin,
                float* __restrict__ out)
{
    constexpr int CIN = 32, COUT = 3, CHUNK = 16;
    __shared__ float sIn[CHUNK][TY+2][TX+2];
    __shared__ float sW[COUT][CHUNK][9];

    const int bx = blockIdx.x * TX, by = blockIdx.y * TY, bb = blockIdx.z;
    const int tid = threadIdx.x;
    const int lx = tid % TX, ly = tid / TX;

    float acc[COUT];
    #pragma unroll
    for (int co = 0; co < COUT; co++) acc[co] = __ldg(&bias[co]);

    for (int c0 = 0; c0 < CIN; c0 += CHUNK) {
        __syncthreads();
        for (int idx = tid; idx < COUT*CHUNK*9; idx += NT) {
            int co = idx / (CHUNK*9);
            int r  = idx - co*(CHUNK*9);
            int ci = r / 9;
            int t  = r - ci*9;
            sW[co][ci][t] = wt[(co*CIN + c0 + ci)*9 + t];
        }
        for (int idx = tid; idx < CHUNK*(TY+2)*(TX+2); idx += NT) {
            int ci = idx / ((TY+2)*(TX+2));
            int r  = idx - ci*((TY+2)*(TX+2));
            int yy = r / (TX+2);
            int xx = r - yy*(TX+2);
            int gy = by + yy - 1, gx = bx + xx - 1;
            float v = 0.f;
            if ((unsigned)gy < (unsigned)H && (unsigned)gx < (unsigned)W)
                v = in[((bb*CIN + c0 + ci)*H + gy)*W + gx];
            sIn[ci][yy][xx] = v;
        }
        __syncthreads();

        #pragma unroll 2
        for (int ci = 0; ci < CHUNK; ci++) {
            float r00 = sIn[ci][ly+0][lx+0], r01 = sIn[ci][ly+0][lx+1], r02 = sIn[ci][ly+0][lx+2];
            float r10 = sIn[ci][ly+1][lx+0], r11 = sIn[ci][ly+1][lx+1], r12 = sIn[ci][ly+1][lx+2];
            float r20 = sIn[ci][ly+2][lx+0], r21 = sIn[ci][ly+2][lx+1], r22 = sIn[ci][ly+2][lx+2];
            #pragma unroll
            for (int co = 0; co < COUT; co++) {
                const float* wp = &sW[co][ci][0];
                float a = acc[co];
                a = fmaf(r00, wp[0], a);
                a = fmaf(r01, wp[1], a);
                a = fmaf(r02, wp[2], a);
                a = fmaf(r10, wp[3], a);
                a = fmaf(r11, wp[4], a);
                a = fmaf(r12, wp[5], a);
                a = fmaf(r20, wp[6], a);
                a = fmaf(r21, wp[7], a);
                a = fmaf(r22, wp[8], a);
                acc[co] = a;
            }
        }
    }

    // conv computed at shifted coords (gy,gx); roll(+4,+4) => write to ((gy+4)%H, (gx+4)%W)
    const int gy = by + ly, gx = bx + lx;
    int oy = gy + 4; if (oy >= H) oy -= H;
    int ox = gx + 4; if (ox >= W) ox -= W;
    #pragma unroll
    for (int co = 0; co < COUT; co++) {
        size_t idx = ((size_t)(bb*COUT + co)*H + oy)*W + ox;
        out[idx] = xin[idx] + acc[co];
    }
}

// ---------------- launcher ----------------
extern "C" void kernel_launch(void* const* d_in, const int* in_sizes, int n_in,
                              void* d_out, int out_size)
{
    (void)in_sizes; (void)n_in; (void)out_size;
    const float* x   = (const float*)d_in[0];
    const float* wo  = (const float*)d_in[19];
    const float* bo  = (const float*)d_in[20];
    const float* pos = (const float*)d_in[21];
    float* out = (float*)d_out;

    float *h1, *h2, *feat, *aout;
    cudaGetSymbolAddress((void**)&h1,   g_h1);
    cudaGetSymbolAddress((void**)&h2,   g_h2);
    cudaGetSymbolAddress((void**)&feat, g_feat);
    cudaGetSymbolAddress((void**)&aout, g_aout);

    dim3 cg(W/TX, H/TY, BATCH);
    for (int br = 0; br < 3; br++) {
        const float* w1 = (const float*)d_in[1 + 6*br];
        const float* b1 = (const float*)d_in[2 + 6*br];
        const float* w2 = (const float*)d_in[3 + 6*br];
        const float* b2 = (const float*)d_in[4 + 6*br];
        const float* w3 = (const float*)d_in[5 + 6*br];
        const float* b3 = (const float*)d_in[6 + 6*br];
        conv3x3_k<3, 64, 3, true,  false><<<cg, NT>>>(x,  w1, b1, h1,   0);
        conv3x3_k<64, 32, 16, true,  false><<<cg, NT>>>(h1, w2, b2, h2,   0);
        conv3x3_k<32, 32, 16, false, true ><<<cg, NT>>>(h2, w3, b3, feat, br*32);
    }
    attn_k<<<dim3(NWIN*NWIN, BATCH), 64>>>(feat, pos, aout);
    conv_out_k<<<cg, NT>>>(aout, wo, bo, x, out);
}

// round 5
// speedup vs baseline: 1.0480x; 1.0480x over previous
#include <cuda_runtime.h>
#include <cstddef>

#define H 384
#define W 384
#define BATCH 2
#define NWIN 48

// conv f32x2 tile geometry: 128 threads, each 4 px (2 packed pairs) x 16 couts
#define CTX 32   // tile width in pixels  (8 thread-cols * 4 px)
#define CTY 16   // tile height
#define SW  34   // smem row stride (32 + 2 halo)
#define SH  18   // smem rows (16 + 2 halo)

// ---------------- scratch (no cudaMalloc allowed) ----------------
__device__ float g_h1[(size_t)BATCH*64*H*W];    // branch conv1 output
__device__ float g_h2[(size_t)BATCH*32*H*W];    // branch conv2 output
__device__ float g_feat[(size_t)BATCH*H*W*96];  // channel-last q|k|v
__device__ float g_aout[(size_t)BATCH*32*H*W];  // attention output (shifted space, NCHW)

// ---------------- packed fp32x2 helpers ----------------
__device__ __forceinline__ unsigned long long pack2(float lo, float hi) {
    unsigned long long r;
    asm("mov.b64 %0, {%1, %2};" : "=l"(r) : "f"(lo), "f"(hi));
    return r;
}
__device__ __forceinline__ unsigned long long fma2(unsigned long long a,
                                                   unsigned long long b,
                                                   unsigned long long c) {
    unsigned long long d;
    asm("fma.rn.f32x2 %0, %1, %2, %3;" : "=l"(d) : "l"(a), "l"(b), "l"(c));
    return d;
}
__device__ __forceinline__ float lo2(unsigned long long v) {
    return __uint_as_float((unsigned)(v & 0xffffffffULL));
}
__device__ __forceinline__ float hi2(unsigned long long v) {
    return __uint_as_float((unsigned)(v >> 32));
}

// ---------------- f32x2 direct 3x3 conv, SAME padding ----------------
// grid: (W/CTX, H/CTY, BATCH * COTOT/16). Each block: 16 couts over a 32x16 tile.
// Each thread: 4 consecutive pixels (2 f32x2 pairs) x 16 couts.
template<int CIN, int CHUNK, int COTOT, bool RELU, bool CHLAST>
__global__ __launch_bounds__(128, 3)
void conv3x3_f2_k(const float* __restrict__ in, const float* __restrict__ wt,
                  const float* __restrict__ bias, float* __restrict__ out,
                  int chlastOff)
{
    __shared__ __align__(16) float sIn[CHUNK][SH][SW];
    __shared__ unsigned long long sW2[16][CHUNK][9];

    constexpr int NHALF = COTOT / 16;
    const int z  = blockIdx.z;
    const int bb = z / NHALF;
    const int coBase = (z - bb*NHALF) * 16;

    const int bx = blockIdx.x * CTX, by = blockIdx.y * CTY;
    const int tid = threadIdx.x;
    const int lx = tid & 7;        // 0..7  -> x0 = bx + lx*4
    const int ly = tid >> 3;       // 0..15
    const int x0l = lx * 4;        // local x of first pixel

    unsigned long long acc[16][2];
    #pragma unroll
    for (int co = 0; co < 16; co++) {
        float b = __ldg(&bias[coBase + co]);
        acc[co][0] = pack2(b, b);
        acc[co][1] = acc[co][0];
    }

    for (int c0 = 0; c0 < CIN; c0 += CHUNK) {
        __syncthreads();
        // packed weights -> smem
        for (int idx = tid; idx < 16*CHUNK*9; idx += 128) {
            int co = idx / (CHUNK*9);
            int r  = idx - co*(CHUNK*9);
            int ci = r / 9;
            int t  = r - ci*9;
            float w = wt[((coBase + co)*CIN + c0 + ci)*9 + t];
            sW2[co][ci][t] = pack2(w, w);
        }
        // input tile + halo -> smem (zero padded)
        for (int idx = tid; idx < CHUNK*SH*SW; idx += 128) {
            int ci = idx / (SH*SW);
            int r  = idx - ci*(SH*SW);
            int yy = r / SW;
            int xx = r - yy*SW;
            int gy = by + yy - 1, gx = bx + xx - 1;
            float v = 0.f;
            if ((unsigned)gy < (unsigned)H && (unsigned)gx < (unsigned)W)
                v = in[((size_t)(bb*CIN + c0 + ci)*H + gy)*W + gx];
            sIn[ci][yy][xx] = v;
        }
        __syncthreads();

        #pragma unroll 1
        for (int ci = 0; ci < CHUNK; ci++) {
            // build 9 taps x 2 pairs
            unsigned long long a[3][3][2];
            #pragma unroll
            for (int dy = 0; dy < 3; dy++) {
                const float* rp = &sIn[ci][ly + dy][x0l];
                float2 p0 = *(const float2*)(rp);      // c0 c1
                float2 p1 = *(const float2*)(rp + 2);  // c2 c3
                float2 p2 = *(const float2*)(rp + 4);  // c4 c5
                unsigned long long u0 = *(const unsigned long long*)&p0;
                unsigned long long u1 = *(const unsigned long long*)&p1;
                unsigned long long u2 = *(const unsigned long long*)&p2;
                a[dy][0][0] = u0;                // {c0,c1}
                a[dy][0][1] = u1;                // {c2,c3}
                a[dy][1][0] = pack2(p0.y, p1.x); // {c1,c2}
                a[dy][1][1] = pack2(p1.y, p2.x); // {c3,c4}
                a[dy][2][0] = u1;                // {c2,c3}
                a[dy][2][1] = u2;                // {c4,c5}
            }
            #pragma unroll
            for (int co = 0; co < 16; co++) {
                #pragma unroll
                for (int t = 0; t < 9; t++) {
                    unsigned long long w = sW2[co][ci][t];
                    acc[co][0] = fma2(a[t/3][t%3][0], w, acc[co][0]);
                    acc[co][1] = fma2(a[t/3][t%3][1], w, acc[co][1]);
                }
            }
        }
    }

    const int gy = by + ly;
    const int gx0 = bx + x0l;

    if constexpr (CHLAST) {
        // feat channel-last: out[((b*H+y)*W+x)*96 + chlastOff + coBase + co]
        #pragma unroll
        for (int p = 0; p < 4; p++) {
            float* op = out + ((size_t)(bb*H + gy)*W + gx0 + p)*96 + chlastOff + coBase;
            #pragma unroll
            for (int cq = 0; cq < 16; cq += 4) {
                float4 v;
                float v0 = (p & 1) ? hi2(acc[cq+0][p>>1]) : lo2(acc[cq+0][p>>1]);
                float v1 = (p & 1) ? hi2(acc[cq+1][p>>1]) : lo2(acc[cq+1][p>>1]);
                float v2 = (p & 1) ? hi2(acc[cq+2][p>>1]) : lo2(acc[cq+2][p>>1]);
                float v3 = (p & 1) ? hi2(acc[cq+3][p>>1]) : lo2(acc[cq+3][p>>1]);
                v.x = RELU ? fmaxf(v0, 0.f) : v0;
                v.y = RELU ? fmaxf(v1, 0.f) : v1;
                v.z = RELU ? fmaxf(v2, 0.f) : v2;
                v.w = RELU ? fmaxf(v3, 0.f) : v3;
                *(float4*)(op + cq) = v;
            }
        }
    } else {
        #pragma unroll
        for (int co = 0; co < 16; co++) {
            float4 v;
            v.x = lo2(acc[co][0]); v.y = hi2(acc[co][0]);
            v.z = lo2(acc[co][1]); v.w = hi2(acc[co][1]);
            if (RELU) {
                v.x = fmaxf(v.x, 0.f); v.y = fmaxf(v.y, 0.f);
                v.z = fmaxf(v.z, 0.f); v.w = fmaxf(v.w, 0.f);
            }
            *(float4*)(out + ((size_t)(bb*COTOT + coBase + co)*H + gy)*W + gx0) = v;
        }
    }
}

// ---------------- shifted-window attention ----------------
__global__ __launch_bounds__(64)
void attn_k(const float* __restrict__ feat, const float* __restrict__ pos,
            float* __restrict__ aout)
{
    __shared__ float sK[64][32];
    __shared__ float sV[64][32];
    __shared__ float sPos[225];

    const int w  = blockIdx.x, bb = blockIdx.y;
    const int wh = w / NWIN, ww = w - wh*NWIN;
    const int tid = threadIdx.x;
    const int iy = tid >> 3, ix = tid & 7;
    const int sy = wh*8 + iy, sx = ww*8 + ix;
    int y = sy + 4; if (y >= H) y -= H;
    int x = sx + 4; if (x >= W) x -= W;

    for (int idx = tid; idx < 64*32; idx += 64) {
        int j = idx >> 5, c = idx & 31;
        int jy = j >> 3, jx = j & 7;
        int yy = wh*8 + jy + 4; if (yy >= H) yy -= H;
        int xx = ww*8 + jx + 4; if (xx >= W) xx -= W;
        const float* p = feat + ((size_t)(bb*H + yy)*W + xx)*96;
        sK[j][c] = p[32 + c];
        sV[j][c] = p[64 + c];
    }
    for (int idx = tid; idx < 225; idx += 64) sPos[idx] = pos[idx];

    float q[32];
    {
        const float* fp = feat + ((size_t)(bb*H + y)*W + x)*96;
        #pragma unroll
        for (int c = 0; c < 32; c += 4) {
            float4 v = *(const float4*)(fp + c);
            q[c] = v.x; q[c+1] = v.y; q[c+2] = v.z; q[c+3] = v.w;
        }
    }
    __syncthreads();

    const bool mR = (wh == NWIN-1);
    const bool mC = (ww == NWIN-1);
    const float scale = 0.35355339059327373f;
    const int posOff = (7 - iy)*15 + (7 - ix);

    #pragma unroll 1
    for (int h = 0; h < 4; h++) {
        float lg[64];
        float mx = -1e30f;
        #pragma unroll
        for (int j = 0; j < 64; j++) {
            const int jy = j >> 3, jx = j & 7;
            float d = 0.f;
            #pragma unroll
            for (int dd = 0; dd < 8; dd++)
                d = fmaf(q[h*8 + dd], sK[j][h*8 + dd], d);
            float l = d*scale + sPos[jy*15 + jx + posOff];
            bool msk = (mR && ((iy >= 4) != (jy >= 4))) ||
                       (mC && ((ix >= 4) != (jx >= 4)));
            l = msk ? -1e30f : l;
            lg[j] = l;
            mx = fmaxf(mx, l);
        }
        float s = 0.f;
        #pragma unroll
        for (int j = 0; j < 64; j++) {
            float e = __expf(lg[j] - mx);
            lg[j] = e;
            s += e;
        }
        const float inv = 1.f / s;
        float oh[8];
        #pragma unroll
        for (int dd = 0; dd < 8; dd++) oh[dd] = 0.f;
        #pragma unroll
        for (int j = 0; j < 64; j++) {
            float p = lg[j];
            #pragma unroll
            for (int dd = 0; dd < 8; dd++)
                oh[dd] = fmaf(p, sV[j][h*8 + dd], oh[dd]);
        }
        #pragma unroll
        for (int dd = 0; dd < 8; dd++)
            aout[((size_t)(bb*32 + h*8 + dd)*H + sy)*W + sx] = oh[dd]*inv;
    }
}

// ---------------- output conv (32->3) + roll(+4,+4) + residual ----------------
#define TX 16
#define TY 8
#define NT (TX*TY)
__global__ __launch_bounds__(NT)
void conv_out_k(const float* __restrict__ in, const float* __restrict__ wt,
                const float* __restrict__ bias, const float* __restrict__ xin,
                float* __restrict__ out)
{
    constexpr int CIN = 32, COUT = 3, CHUNK = 16;
    __shared__ float sInb[CHUNK][TY+2][TX+2];
    __shared__ float sWb[COUT][CHUNK][9];

    const int bx = blockIdx.x * TX, by = blockIdx.y * TY, bb = blockIdx.z;
    const int tid = threadIdx.x;
    const int lx = tid % TX, ly = tid / TX;

    float acc[COUT];
    #pragma unroll
    for (int co = 0; co < COUT; co++) acc[co] = __ldg(&bias[co]);

    for (int c0 = 0; c0 < CIN; c0 += CHUNK) {
        __syncthreads();
        for (int idx = tid; idx < COUT*CHUNK*9; idx += NT) {
            int co = idx / (CHUNK*9);
            int r  = idx - co*(CHUNK*9);
            int ci = r / 9;
            int t  = r - ci*9;
            sWb[co][ci][t] = wt[(co*CIN + c0 + ci)*9 + t];
        }
        for (int idx = tid; idx < CHUNK*(TY+2)*(TX+2); idx += NT) {
            int ci = idx / ((TY+2)*(TX+2));
            int r  = idx - ci*((TY+2)*(TX+2));
            int yy = r / (TX+2);
            int xx = r - yy*(TX+2);
            int gy = by + yy - 1, gx = bx + xx - 1;
            float v = 0.f;
            if ((unsigned)gy < (unsigned)H && (unsigned)gx < (unsigned)W)
                v = in[((size_t)(bb*CIN + c0 + ci)*H + gy)*W + gx];
            sInb[ci][yy][xx] = v;
        }
        __syncthreads();

        #pragma unroll 2
        for (int ci = 0; ci < CHUNK; ci++) {
            float r00 = sInb[ci][ly+0][lx+0], r01 = sInb[ci][ly+0][lx+1], r02 = sInb[ci][ly+0][lx+2];
            float r10 = sInb[ci][ly+1][lx+0], r11 = sInb[ci][ly+1][lx+1], r12 = sInb[ci][ly+1][lx+2];
            float r20 = sInb[ci][ly+2][lx+0], r21 = sInb[ci][ly+2][lx+1], r22 = sInb[ci][ly+2][lx+2];
            #pragma unroll
            for (int co = 0; co < COUT; co++) {
                const float* wp = &sWb[co][ci][0];
                float a = acc[co];
                a = fmaf(r00, wp[0], a);
                a = fmaf(r01, wp[1], a);
                a = fmaf(r02, wp[2], a);
                a = fmaf(r10, wp[3], a);
                a = fmaf(r11, wp[4], a);
                a = fmaf(r12, wp[5], a);
                a = fmaf(r20, wp[6], a);
                a = fmaf(r21, wp[7], a);
                a = fmaf(r22, wp[8], a);
                acc[co] = a;
            }
        }
    }

    const int gy = by + ly, gx = bx + lx;
    int oy = gy + 4; if (oy >= H) oy -= H;
    int ox = gx + 4; if (ox >= W) ox -= W;
    #pragma unroll
    for (int co = 0; co < COUT; co++) {
        size_t idx = ((size_t)(bb*COUT + co)*H + oy)*W + ox;
        out[idx] = xin[idx] + acc[co];
    }
}

// ---------------- launcher ----------------
extern "C" void kernel_launch(void* const* d_in, const int* in_sizes, int n_in,
                              void* d_out, int out_size)
{
    (void)in_sizes; (void)n_in; (void)out_size;
    const float* x   = (const float*)d_in[0];
    const float* wo  = (const float*)d_in[19];
    const float* bo  = (const float*)d_in[20];
    const float* pos = (const float*)d_in[21];
    float* out = (float*)d_out;

    float *h1, *h2, *feat, *aout;
    cudaGetSymbolAddress((void**)&h1,   g_h1);
    cudaGetSymbolAddress((void**)&h2,   g_h2);
    cudaGetSymbolAddress((void**)&feat, g_feat);
    cudaGetSymbolAddress((void**)&aout, g_aout);

    dim3 g1(W/CTX, H/CTY, BATCH * (64/16));  // conv1: 64 couts -> 4 halves
    dim3 g2(W/CTX, H/CTY, BATCH * (32/16));  // conv2/conv3: 32 couts -> 2 halves

    for (int br = 0; br < 3; br++) {
        const float* w1 = (const float*)d_in[1 + 6*br];
        const float* b1 = (const float*)d_in[2 + 6*br];
        const float* w2 = (const float*)d_in[3 + 6*br];
        const float* b2 = (const float*)d_in[4 + 6*br];
        const float* w3 = (const float*)d_in[5 + 6*br];
        const float* b3 = (const float*)d_in[6 + 6*br];
        conv3x3_f2_k<3,  3, 64, true,  false><<<g1, 128>>>(x,  w1, b1, h1,   0);
        conv3x3_f2_k<64, 8, 32, true,  false><<<g2, 128>>>(h1, w2, b2, h2,   0);
        conv3x3_f2_k<32, 8, 32, false, true ><<<g2, 128>>>(h2, w3, b3, feat, br*32);
    }
    attn_k<<<dim3(NWIN*NWIN, BATCH), 64>>>(feat, pos, aout);
    conv_out_k<<<dim3(W/TX, H/TY, BATCH), NT>>>(aout, wo, bo, x, out);
}

// round 6
// speedup vs baseline: 2.0733x; 1.9784x over previous
#include <cuda_runtime.h>
#include <cstdint>
#include <cstddef>

#define H 384
#define W 384
#define BATCH 2
#define NWIN 48

// ---------------- scratch ----------------
__device__ float g_h1[(size_t)BATCH*H*W*64];    // conv1 out, channel-last [b][y][x][64], tf32-rounded
__device__ float g_h2[(size_t)BATCH*H*W*32];    // conv2 out, channel-last [b][y][x][32], tf32-rounded
__device__ float g_feat[(size_t)BATCH*H*W*96];  // q|k|v channel-last
__device__ float g_aout[(size_t)BATCH*32*H*W];  // attention out (shifted space, NCHW)

// ---------------- helpers ----------------
__device__ __forceinline__ unsigned long long pack2(float lo, float hi) {
    unsigned long long r;
    asm("mov.b64 %0, {%1, %2};" : "=l"(r) : "f"(lo), "f"(hi));
    return r;
}
__device__ __forceinline__ unsigned long long fma2(unsigned long long a,
                                                   unsigned long long b,
                                                   unsigned long long c) {
    unsigned long long d;
    asm("fma.rn.f32x2 %0, %1, %2, %3;" : "=l"(d) : "l"(a), "l"(b), "l"(c));
    return d;
}
__device__ __forceinline__ float lo2(unsigned long long v) {
    return __uint_as_float((unsigned)(v & 0xffffffffULL));
}
__device__ __forceinline__ float hi2(unsigned long long v) {
    return __uint_as_float((unsigned)(v >> 32));
}
__device__ __forceinline__ float to_tf32(float f) {
    uint32_t u;
    asm("cvt.rna.tf32.f32 %0, %1;" : "=r"(u) : "f"(f));
    return __uint_as_float(u);
}
__device__ __forceinline__ void mma_tf32(float& c0, float& c1, float& c2, float& c3,
                                         uint32_t a0, uint32_t a1, uint32_t a2, uint32_t a3,
                                         uint32_t b0, uint32_t b1) {
    asm volatile("mma.sync.aligned.m16n8k8.row.col.f32.tf32.tf32.f32 "
                 "{%0,%1,%2,%3}, {%4,%5,%6,%7}, {%8,%9}, {%0,%1,%2,%3};"
                 : "+f"(c0), "+f"(c1), "+f"(c2), "+f"(c3)
                 : "r"(a0), "r"(a1), "r"(a2), "r"(a3), "r"(b0), "r"(b1));
}

// =====================================================================
// conv1: 3->64, direct f32x2, writes channel-last [b][y][x][64] tf32
// =====================================================================
#define CTX 32
#define CTY 16
__global__ __launch_bounds__(128, 3)
void conv1_k(const float* __restrict__ in, const float* __restrict__ wt,
             const float* __restrict__ bias, float* __restrict__ out)
{
    __shared__ __align__(16) float sIn[3][18][34];
    __shared__ unsigned long long sW2[16][3][9];

    const int z  = blockIdx.z;
    const int bb = z >> 2;
    const int coBase = (z & 3) * 16;
    const int bx = blockIdx.x * CTX, by = blockIdx.y * CTY;
    const int tid = threadIdx.x;
    const int lx = tid & 7, ly = tid >> 3;
    const int x0l = lx * 4;

    // weights (432 entries, few iterations)
    for (int idx = tid; idx < 16*27; idx += 128) {
        int co = idx / 27;
        int r  = idx - co*27;
        int ci = r / 9;
        int t  = r - ci*9;
        float w = wt[((coBase + co)*3 + ci)*9 + t];
        sW2[co][ci][t] = pack2(w, w);
    }
    // input fill: 2D mapping, no big divisions
    {
        const int ty = tid >> 5, tx = tid & 31;
        for (int ci = 0; ci < 3; ci++)
            for (int yy = ty; yy < 18; yy += 4)
                for (int xx = tx; xx < 34; xx += 32) {
                    int gy = by + yy - 1, gx = bx + xx - 1;
                    float v = 0.f;
                    if ((unsigned)gy < (unsigned)H && (unsigned)gx < (unsigned)W)
                        v = in[((size_t)(bb*3 + ci)*H + gy)*W + gx];
                    sIn[ci][yy][xx] = v;
                }
    }
    __syncthreads();

    unsigned long long acc[16][2];
    #pragma unroll
    for (int co = 0; co < 16; co++) {
        float b = __ldg(&bias[coBase + co]);
        acc[co][0] = pack2(b, b);
        acc[co][1] = acc[co][0];
    }

    #pragma unroll
    for (int ci = 0; ci < 3; ci++) {
        unsigned long long a[3][3][2];
        #pragma unroll
        for (int dy = 0; dy < 3; dy++) {
            const float* rp = &sIn[ci][ly + dy][x0l];
            float2 p0 = *(const float2*)(rp);
            float2 p1 = *(const float2*)(rp + 2);
            float2 p2 = *(const float2*)(rp + 4);
            a[dy][0][0] = *(const unsigned long long*)&p0;
            a[dy][0][1] = *(const unsigned long long*)&p1;
            a[dy][1][0] = pack2(p0.y, p1.x);
            a[dy][1][1] = pack2(p1.y, p2.x);
            a[dy][2][0] = *(const unsigned long long*)&p1;
            a[dy][2][1] = *(const unsigned long long*)&p2;
        }
        #pragma unroll
        for (int co = 0; co < 16; co++) {
            #pragma unroll
            for (int t = 0; t < 9; t++) {
                unsigned long long w = sW2[co][ci][t];
                acc[co][0] = fma2(a[t/3][t%3][0], w, acc[co][0]);
                acc[co][1] = fma2(a[t/3][t%3][1], w, acc[co][1]);
            }
        }
    }

    const int gy = by + ly, gx0 = bx + x0l;
    #pragma unroll
    for (int p = 0; p < 4; p++) {
        float* op = out + ((size_t)(bb*H + gy)*W + gx0 + p)*64 + coBase;
        #pragma unroll
        for (int cq = 0; cq < 16; cq += 4) {
            float4 v;
            float v0 = (p & 1) ? hi2(acc[cq+0][p>>1]) : lo2(acc[cq+0][p>>1]);
            float v1 = (p & 1) ? hi2(acc[cq+1][p>>1]) : lo2(acc[cq+1][p>>1]);
            float v2 = (p & 1) ? hi2(acc[cq+2][p>>1]) : lo2(acc[cq+2][p>>1]);
            float v3 = (p & 1) ? hi2(acc[cq+3][p>>1]) : lo2(acc[cq+3][p>>1]);
            v.x = to_tf32(fmaxf(v0, 0.f));
            v.y = to_tf32(fmaxf(v1, 0.f));
            v.z = to_tf32(fmaxf(v2, 0.f));
            v.w = to_tf32(fmaxf(v3, 0.f));
            *(float4*)(op + cq) = v;
        }
    }
}

// =====================================================================
// gemm conv (3x3 as 9 shifted 1x1): channel-last in -> channel-last out
// block: 256 thr (8 warps), tile 2 rows x 128 px, COUT=32
// smem: sA[4][130][36] + sBf[9*1024] fragment-ordered
// =====================================================================
#define GA_ROWPX 36              // padded ci stride per pixel (conflict-free frags, 16B aligned)
#define GA_FLOATS (4*130*GA_ROWPX)
#define GB_FLOATS (9*1024)
#define GEMM_SMEM_BYTES ((GA_FLOATS + GB_FLOATS)*4)

template<int CIN, int NCHUNK, int OSTR, bool RELU, bool TF32OUT>
__global__ __launch_bounds__(256, 2)
void gemm_conv_k(const float* __restrict__ in_cl, const float* __restrict__ wt,
                 const float* __restrict__ bias, float* __restrict__ out, int outOff)
{
    extern __shared__ float smem[];
    float* sA  = smem;                 // [4][130][36]
    float* sBf = smem + GA_FLOATS;     // fragment-ordered weights

    const int bb = blockIdx.z;
    const int x0 = blockIdx.x * 128;
    const int y0 = blockIdx.y * 2;
    const int tid = threadIdx.x;
    const int warp = tid >> 5, lane = tid & 31;
    const int warpRow = warp >> 2;          // 0..1
    const int pxBase  = (warp & 3) * 32;    // 0,32,64,96
    const int groupId = lane >> 2, quad = lane & 3;

    float acc[2][4][4];
    #pragma unroll
    for (int n = 0; n < 4; n++) {
        float b0 = __ldg(&bias[n*8 + quad*2 + 0]);
        float b1 = __ldg(&bias[n*8 + quad*2 + 1]);
        #pragma unroll
        for (int m = 0; m < 2; m++) {
            acc[m][n][0] = b0; acc[m][n][1] = b1;
            acc[m][n][2] = b0; acc[m][n][3] = b1;
        }
    }

    for (int ch = 0; ch < NCHUNK; ch++) {
        __syncthreads();
        // ---- fill A slab: rows y0-1..y0+2, px x0-1..x0+128, ci chunk of 32 ----
        #pragma unroll
        for (int r = 0; r < 4; r++) {
            int y = y0 - 1 + r;
            bool yin = (unsigned)y < (unsigned)H;
            for (int i = tid; i < 130*8; i += 256) {
                int px = i >> 3, v = i & 7;
                int x = x0 - 1 + px;
                float4 val = make_float4(0.f, 0.f, 0.f, 0.f);
                if (yin && (unsigned)x < (unsigned)W)
                    val = *(const float4*)(in_cl + ((size_t)(bb*H + y)*W + x)*CIN + ch*32 + v*4);
                *(float4*)(sA + (r*130 + px)*GA_ROWPX + v*4) = val;
            }
        }
        // ---- fill B fragment-ordered: idx = dydx*1024 + kk*256 + n*64 + lane*2 + j ----
        for (int idx = tid; idx < 9216; idx += 256) {
            int j    = idx & 1;
            int ln   = (idx >> 1) & 31;
            int n    = (idx >> 6) & 3;
            int kk   = (idx >> 8) & 3;
            int dydx = idx >> 10;
            int ci = ch*32 + kk*8 + (ln & 3) + 4*j;
            int co = n*8 + (ln >> 2);
            sBf[idx] = to_tf32(wt[(co*CIN + ci)*9 + dydx]);
        }
        __syncthreads();

        // ---- mainloop: 9 shifts x 4 k-steps ----
        #pragma unroll
        for (int dy = 0; dy < 3; dy++) {
            #pragma unroll
            for (int dx = 0; dx < 3; dx++) {
                const float* pa = sA + ((warpRow + dy)*130 + pxBase + dx + groupId)*GA_ROWPX + quad;
                const float* pb = sBf + (dy*3 + dx)*1024 + lane*2;
                #pragma unroll
                for (int kk = 0; kk < 4; kk++) {
                    uint32_t b0[4], b1[4];
                    #pragma unroll
                    for (int n = 0; n < 4; n++) {
                        float2 bv = *(const float2*)(pb + kk*256 + n*64);
                        b0[n] = __float_as_uint(bv.x);
                        b1[n] = __float_as_uint(bv.y);
                    }
                    #pragma unroll
                    for (int m = 0; m < 2; m++) {
                        const float* pm = pa + m*16*GA_ROWPX + kk*8;
                        uint32_t a0 = __float_as_uint(pm[0]);
                        uint32_t a1 = __float_as_uint(pm[8*GA_ROWPX]);
                        uint32_t a2 = __float_as_uint(pm[4]);
                        uint32_t a3 = __float_as_uint(pm[8*GA_ROWPX + 4]);
                        #pragma unroll
                        for (int n = 0; n < 4; n++)
                            mma_tf32(acc[m][n][0], acc[m][n][1], acc[m][n][2], acc[m][n][3],
                                     a0, a1, a2, a3, b0[n], b1[n]);
                    }
                }
            }
        }
    }

    // ---- epilogue ----
    const int yOut = y0 + warpRow;
    #pragma unroll
    for (int m = 0; m < 2; m++) {
        #pragma unroll
        for (int hh = 0; hh < 2; hh++) {
            int px = pxBase + m*16 + groupId + hh*8;
            float* op = out + ((size_t)(bb*H + yOut)*W + x0 + px)*OSTR + outOff + quad*2;
            #pragma unroll
            for (int n = 0; n < 4; n++) {
                float v0 = acc[m][n][hh*2 + 0];
                float v1 = acc[m][n][hh*2 + 1];
                if (RELU) { v0 = fmaxf(v0, 0.f); v1 = fmaxf(v1, 0.f); }
                if (TF32OUT) { v0 = to_tf32(v0); v1 = to_tf32(v1); }
                float2 v = make_float2(v0, v1);
                *(float2*)(op + n*8) = v;
            }
        }
    }
}

// =====================================================================
// shifted-window attention (unchanged, reads feat channel-last 96)
// =====================================================================
__global__ __launch_bounds__(64)
void attn_k(const float* __restrict__ feat, const float* __restrict__ pos,
            float* __restrict__ aout)
{
    __shared__ float sK[64][32];
    __shared__ float sV[64][32];
    __shared__ float sPos[225];

    const int w  = blockIdx.x, bb = blockIdx.y;
    const int wh = w / NWIN, ww = w - wh*NWIN;
    const int tid = threadIdx.x;
    const int iy = tid >> 3, ix = tid & 7;
    const int sy = wh*8 + iy, sx = ww*8 + ix;
    int y = sy + 4; if (y >= H) y -= H;
    int x = sx + 4; if (x >= W) x -= W;

    for (int idx = tid; idx < 64*32; idx += 64) {
        int j = idx >> 5, c = idx & 31;
        int jy = j >> 3, jx = j & 7;
        int yy = wh*8 + jy + 4; if (yy >= H) yy -= H;
        int xx = ww*8 + jx + 4; if (xx >= W) xx -= W;
        const float* p = feat + ((size_t)(bb*H + yy)*W + xx)*96;
        sK[j][c] = p[32 + c];
        sV[j][c] = p[64 + c];
    }
    for (int idx = tid; idx < 225; idx += 64) sPos[idx] = pos[idx];

    float q[32];
    {
        const float* fp = feat + ((size_t)(bb*H + y)*W + x)*96;
        #pragma unroll
        for (int c = 0; c < 32; c += 4) {
            float4 v = *(const float4*)(fp + c);
            q[c] = v.x; q[c+1] = v.y; q[c+2] = v.z; q[c+3] = v.w;
        }
    }
    __syncthreads();

    const bool mR = (wh == NWIN-1);
    const bool mC = (ww == NWIN-1);
    const float scale = 0.35355339059327373f;
    const int posOff = (7 - iy)*15 + (7 - ix);

    #pragma unroll 1
    for (int h = 0; h < 4; h++) {
        float lg[64];
        float mx = -1e30f;
        #pragma unroll
        for (int j = 0; j < 64; j++) {
            const int jy = j >> 3, jx = j & 7;
            float d = 0.f;
            #pragma unroll
            for (int dd = 0; dd < 8; dd++)
                d = fmaf(q[h*8 + dd], sK[j][h*8 + dd], d);
            float l = d*scale + sPos[jy*15 + jx + posOff];
            bool msk = (mR && ((iy >= 4) != (jy >= 4))) ||
                       (mC && ((ix >= 4) != (jx >= 4)));
            l = msk ? -1e30f : l;
            lg[j] = l;
            mx = fmaxf(mx, l);
        }
        float s = 0.f;
        #pragma unroll
        for (int j = 0; j < 64; j++) {
            float e = __expf(lg[j] - mx);
            lg[j] = e;
            s += e;
        }
        const float inv = 1.f / s;
        float oh[8];
        #pragma unroll
        for (int dd = 0; dd < 8; dd++) oh[dd] = 0.f;
        #pragma unroll
        for (int j = 0; j < 64; j++) {
            float p = lg[j];
            #pragma unroll
            for (int dd = 0; dd < 8; dd++)
                oh[dd] = fmaf(p, sV[j][h*8 + dd], oh[dd]);
        }
        #pragma unroll
        for (int dd = 0; dd < 8; dd++)
            aout[((size_t)(bb*32 + h*8 + dd)*H + sy)*W + sx] = oh[dd]*inv;
    }
}

// =====================================================================
// output conv (32->3) + roll(+4,+4) + residual (unchanged)
// =====================================================================
#define TXO 16
#define TYO 8
#define NTO (TXO*TYO)
__global__ __launch_bounds__(NTO)
void conv_out_k(const float* __restrict__ in, const float* __restrict__ wt,
                const float* __restrict__ bias, const float* __restrict__ xin,
                float* __restrict__ out)
{
    constexpr int CIN = 32, COUT = 3, CHUNK = 16;
    __shared__ float sInb[CHUNK][TYO+2][TXO+2];
    __shared__ float sWb[COUT][CHUNK][9];

    const int bx = blockIdx.x * TXO, by = blockIdx.y * TYO, bb = blockIdx.z;
    const int tid = threadIdx.x;
    const int lx = tid % TXO, ly = tid / TXO;

    float acc[COUT];
    #pragma unroll
    for (int co = 0; co < COUT; co++) acc[co] = __ldg(&bias[co]);

    for (int c0 = 0; c0 < CIN; c0 += CHUNK) {
        __syncthreads();
        for (int idx = tid; idx < COUT*CHUNK*9; idx += NTO) {
            int co = idx / (CHUNK*9);
            int r  = idx - co*(CHUNK*9);
            int ci = r / 9;
            int t  = r - ci*9;
            sWb[co][ci][t] = wt[(co*CIN + c0 + ci)*9 + t];
        }
        {
            const int ty = tid >> 5, tx = tid & 31;
            for (int ci = 0; ci < CHUNK; ci++)
                for (int yy = ty; yy < TYO+2; yy += 4)
                    for (int xx = tx; xx < TXO+2; xx += 32) {
                        int gy = by + yy - 1, gx = bx + xx - 1;
                        float v = 0.f;
                        if ((unsigned)gy < (unsigned)H && (unsigned)gx < (unsigned)W)
                            v = in[((size_t)(bb*CIN + c0 + ci)*H + gy)*W + gx];
                        sInb[ci][yy][xx] = v;
                    }
        }
        __syncthreads();

        #pragma unroll 2
        for (int ci = 0; ci < CHUNK; ci++) {
            float r00 = sInb[ci][ly+0][lx+0], r01 = sInb[ci][ly+0][lx+1], r02 = sInb[ci][ly+0][lx+2];
            float r10 = sInb[ci][ly+1][lx+0], r11 = sInb[ci][ly+1][lx+1], r12 = sInb[ci][ly+1][lx+2];
            float r20 = sInb[ci][ly+2][lx+0], r21 = sInb[ci][ly+2][lx+1], r22 = sInb[ci][ly+2][lx+2];
            #pragma unroll
            for (int co = 0; co < COUT; co++) {
                const float* wp = &sWb[co][ci][0];
                float a = acc[co];
                a = fmaf(r00, wp[0], a);
                a = fmaf(r01, wp[1], a);
                a = fmaf(r02, wp[2], a);
                a = fmaf(r10, wp[3], a);
                a = fmaf(r11, wp[4], a);
                a = fmaf(r12, wp[5], a);
                a = fmaf(r20, wp[6], a);
                a = fmaf(r21, wp[7], a);
                a = fmaf(r22, wp[8], a);
                acc[co] = a;
            }
        }
    }

    const int gy = by + ly, gx = bx + lx;
    int oy = gy + 4; if (oy >= H) oy -= H;
    int ox = gx + 4; if (ox >= W) ox -= W;
    #pragma unroll
    for (int co = 0; co < COUT; co++) {
        size_t idx = ((size_t)(bb*COUT + co)*H + oy)*W + ox;
        out[idx] = xin[idx] + acc[co];
    }
}

// ---------------- launcher ----------------
extern "C" void kernel_launch(void* const* d_in, const int* in_sizes, int n_in,
                              void* d_out, int out_size)
{
    (void)in_sizes; (void)n_in; (void)out_size;
    const float* x   = (const float*)d_in[0];
    const float* wo  = (const float*)d_in[19];
    const float* bo  = (const float*)d_in[20];
    const float* pos = (const float*)d_in[21];
    float* out = (float*)d_out;

    float *h1, *h2, *feat, *aout;
    cudaGetSymbolAddress((void**)&h1,   g_h1);
    cudaGetSymbolAddress((void**)&h2,   g_h2);
    cudaGetSymbolAddress((void**)&feat, g_feat);
    cudaGetSymbolAddress((void**)&aout, g_aout);

    cudaFuncSetAttribute(gemm_conv_k<64,2,32,true,true>,
                         cudaFuncAttributeMaxDynamicSharedMemorySize, GEMM_SMEM_BYTES);
    cudaFuncSetAttribute(gemm_conv_k<32,1,96,false,false>,
                         cudaFuncAttributeMaxDynamicSharedMemorySize, GEMM_SMEM_BYTES);

    dim3 g1(W/CTX, H/CTY, BATCH*4);
    dim3 gg(W/128, H/2, BATCH);

    for (int br = 0; br < 3; br++) {
        const float* w1 = (const float*)d_in[1 + 6*br];
        const float* b1 = (const float*)d_in[2 + 6*br];
        const float* w2 = (const float*)d_in[3 + 6*br];
        const float* b2 = (const float*)d_in[4 + 6*br];
        const float* w3 = (const float*)d_in[5 + 6*br];
        const float* b3 = (const float*)d_in[6 + 6*br];
        conv1_k<<<g1, 128>>>(x, w1, b1, h1);
        gemm_conv_k<64,2,32,true,true><<<gg, 256, GEMM_SMEM_BYTES>>>(h1, w2, b2, h2, 0);
        gemm_conv_k<32,1,96,false,false><<<gg, 256, GEMM_SMEM_BYTES>>>(h2, w3, b3, feat, br*32);
    }
    attn_k<<<dim3(NWIN*NWIN, BATCH), 64>>>(feat, pos, aout);
    conv_out_k<<<dim3(W/TXO, H/TYO, BATCH), NTO>>>(aout, wo, bo, x, out);
}

// round 7
// speedup vs baseline: 2.7580x; 1.3303x over previous
#include <cuda_runtime.h>
#include <cstdint>
#include <cstddef>

#define H 384
#define W 384
#define BATCH 2
#define NWIN 48

// ---------------- scratch ----------------
__device__ float g_h1[(size_t)BATCH*H*W*64];    // conv1 out, channel-last, tf32
__device__ float g_h2[(size_t)BATCH*H*W*32];    // conv2 out, channel-last, tf32
__device__ float g_feat[(size_t)BATCH*H*W*96];  // q|k|v channel-last
__device__ float g_aout[(size_t)BATCH*32*H*W];  // attention out (shifted space, NCHW)
// fragment-ordered tf32 weights (per conv type, 3 branches each)
__device__ float g_bf1[3*4608];
__device__ float g_bf2[3*18432];
__device__ float g_bf3[3*9216];

// ---------------- helpers ----------------
__device__ __forceinline__ float to_tf32(float f) {
    uint32_t u;
    asm("cvt.rna.tf32.f32 %0, %1;" : "=r"(u) : "f"(f));
    return __uint_as_float(u);
}
__device__ __forceinline__ void mma_tf32(float& c0, float& c1, float& c2, float& c3,
                                         uint32_t a0, uint32_t a1, uint32_t a2, uint32_t a3,
                                         uint32_t b0, uint32_t b1) {
    asm volatile("mma.sync.aligned.m16n8k8.row.col.f32.tf32.tf32.f32 "
                 "{%0,%1,%2,%3}, {%4,%5,%6,%7}, {%8,%9}, {%0,%1,%2,%3};"
                 : "+f"(c0), "+f"(c1), "+f"(c2), "+f"(c3)
                 : "r"(a0), "r"(a1), "r"(a2), "r"(a3), "r"(b0), "r"(b1));
}

// =====================================================================
// B-fragment prep: wt (co-major, (COUT,CINREAL,3,3)) -> fragment order
// layout: idx = ((ch*9 + dydx)*KSTEPS + kk)*NGRP*64 + n*64 + lane*2 + j
// ci = ch*CHK + kk*8 + (lane&3) + 4j ; co = n*8 + (lane>>2)
// =====================================================================
template<int CHK, int KSTEPS, int NCHUNK, int NGRP, int CINREAL>
__global__ void prep_b_k(const float* __restrict__ w0, const float* __restrict__ w1,
                         const float* __restrict__ w2, float* __restrict__ outBase)
{
    constexpr int SZ = NCHUNK*9*KSTEPS*NGRP*64;
    int idx = blockIdx.x*256 + threadIdx.x;
    if (idx >= SZ) return;
    const float* wt = blockIdx.y == 0 ? w0 : (blockIdx.y == 1 ? w1 : w2);
    float* outp = outBase + blockIdx.y*SZ;
    int j  = idx & 1;
    int ln = (idx >> 1) & 31;
    int n  = (idx >> 6) % NGRP;
    int r2 = idx / (64*NGRP);
    int kk = r2 % KSTEPS;
    int r3 = r2 / KSTEPS;
    int dydx = r3 % 9;
    int ch   = r3 / 9;
    int ci = ch*CHK + kk*8 + (ln & 3) + 4*j;
    int co = n*8 + (ln >> 2);
    float v = 0.f;
    if (ci < CINREAL) v = to_tf32(wt[(co*CINREAL + ci)*9 + dydx]);
    outp[idx] = v;
}

// =====================================================================
// implicit-GEMM 3x3 conv (9 shifted 1x1). block 256 thr, tile 2 rows x 128 px.
// A slab in smem [4 rows][130 px][PAD]; B read from global fragment buffer.
// NCHW3: input is NCHW 3-channel (conv1), padded to 8 k-slots.
// =====================================================================
template<int CHK, int PAD, int KSTEPS, int NCHUNK, int NGRP, int CINTOT,
         int OSTR, bool RELU, bool TF32OUT, bool NCHW3>
__global__ __launch_bounds__(256, 2)
void gemm_conv_k(const float* __restrict__ in, const float* __restrict__ gB,
                 const float* __restrict__ bias, float* __restrict__ out, int outOff)
{
    extern __shared__ float sA[];   // [4][130][PAD]

    const int bb = blockIdx.z;
    const int x0 = blockIdx.x * 128;
    const int y0 = blockIdx.y * 2;
    const int tid = threadIdx.x;
    const int warp = tid >> 5, lane = tid & 31;
    const int warpRow = warp >> 2;          // 0..1
    const int pxBase  = (warp & 3) * 32;    // 0,32,64,96
    const int groupId = lane >> 2, quad = lane & 3;

    float acc[2][NGRP][4];
    #pragma unroll
    for (int n = 0; n < NGRP; n++) {
        float b0 = __ldg(&bias[n*8 + quad*2 + 0]);
        float b1 = __ldg(&bias[n*8 + quad*2 + 1]);
        #pragma unroll
        for (int m = 0; m < 2; m++) {
            acc[m][n][0] = b0; acc[m][n][1] = b1;
            acc[m][n][2] = b0; acc[m][n][3] = b1;
        }
    }

    #pragma unroll 1
    for (int ch = 0; ch < NCHUNK; ch++) {
        __syncthreads();
        if constexpr (NCHW3) {
            // conv1: gather 3 NCHW planes into 8 channel-last slots (5 zero)
            #pragma unroll
            for (int r = 0; r < 4; r++) {
                int y = y0 - 1 + r;
                bool yin = (unsigned)y < (unsigned)H;
                if (tid < 130) {
                    int x = x0 - 1 + tid;
                    float c0 = 0.f, c1 = 0.f, c2 = 0.f;
                    if (yin && (unsigned)x < (unsigned)W) {
                        c0 = in[((size_t)(bb*3 + 0)*H + y)*W + x];
                        c1 = in[((size_t)(bb*3 + 1)*H + y)*W + x];
                        c2 = in[((size_t)(bb*3 + 2)*H + y)*W + x];
                    }
                    float* dst = sA + (r*130 + tid)*PAD;
                    *(float4*)dst     = make_float4(to_tf32(c0), to_tf32(c1), to_tf32(c2), 0.f);
                    *(float4*)(dst+4) = make_float4(0.f, 0.f, 0.f, 0.f);
                }
            }
        } else {
            constexpr int VPP = CHK/4;   // float4 per pixel
            #pragma unroll
            for (int r = 0; r < 4; r++) {
                int y = y0 - 1 + r;
                bool yin = (unsigned)y < (unsigned)H;
                for (int i = tid; i < 130*VPP; i += 256) {
                    int px = i / VPP, v = i % VPP;
                    int x = x0 - 1 + px;
                    float4 val = make_float4(0.f, 0.f, 0.f, 0.f);
                    if (yin && (unsigned)x < (unsigned)W)
                        val = *(const float4*)(in + ((size_t)(bb*H + y)*W + x)*CINTOT + ch*CHK + v*4);
                    *(float4*)(sA + (r*130 + px)*PAD + v*4) = val;
                }
            }
        }
        __syncthreads();

        #pragma unroll
        for (int dy = 0; dy < 3; dy++) {
            #pragma unroll
            for (int dx = 0; dx < 3; dx++) {
                const float* pa = sA + ((warpRow + dy)*130 + pxBase + dx + groupId)*PAD + quad;
                const float* pb = gB + (size_t)((ch*9 + dy*3 + dx)*KSTEPS)*(NGRP*64) + lane*2;
                #pragma unroll
                for (int kk = 0; kk < KSTEPS; kk++) {
                    uint32_t b0[NGRP], b1[NGRP];
                    #pragma unroll
                    for (int n = 0; n < NGRP; n++) {
                        float2 bv = __ldg((const float2*)(pb + (kk*NGRP + n)*64));
                        b0[n] = __float_as_uint(bv.x);
                        b1[n] = __float_as_uint(bv.y);
                    }
                    #pragma unroll
                    for (int m = 0; m < 2; m++) {
                        const float* pm = pa + m*16*PAD + kk*8;
                        uint32_t a0 = __float_as_uint(pm[0]);
                        uint32_t a1 = __float_as_uint(pm[8*PAD]);
                        uint32_t a2 = __float_as_uint(pm[4]);
                        uint32_t a3 = __float_as_uint(pm[8*PAD + 4]);
                        #pragma unroll
                        for (int n = 0; n < NGRP; n++)
                            mma_tf32(acc[m][n][0], acc[m][n][1], acc[m][n][2], acc[m][n][3],
                                     a0, a1, a2, a3, b0[n], b1[n]);
                    }
                }
            }
        }
    }

    // ---- epilogue ----
    const int yOut = y0 + warpRow;
    #pragma unroll
    for (int m = 0; m < 2; m++) {
        #pragma unroll
        for (int hh = 0; hh < 2; hh++) {
            int px = pxBase + m*16 + groupId + hh*8;
            float* op = out + ((size_t)(bb*H + yOut)*W + x0 + px)*OSTR + outOff + quad*2;
            #pragma unroll
            for (int n = 0; n < NGRP; n++) {
                float v0 = acc[m][n][hh*2 + 0];
                float v1 = acc[m][n][hh*2 + 1];
                if (RELU) { v0 = fmaxf(v0, 0.f); v1 = fmaxf(v1, 0.f); }
                if (TF32OUT) { v0 = to_tf32(v0); v1 = to_tf32(v1); }
                *(float2*)(op + n*8) = make_float2(v0, v1);
            }
        }
    }
}

// =====================================================================
// shifted-window attention (reads feat channel-last 96)
// =====================================================================
__global__ __launch_bounds__(64)
void attn_k(const float* __restrict__ feat, const float* __restrict__ pos,
            float* __restrict__ aout)
{
    __shared__ float sK[64][32];
    __shared__ float sV[64][32];
    __shared__ float sPos[225];

    const int w  = blockIdx.x, bb = blockIdx.y;
    const int wh = w / NWIN, ww = w - wh*NWIN;
    const int tid = threadIdx.x;
    const int iy = tid >> 3, ix = tid & 7;
    const int sy = wh*8 + iy, sx = ww*8 + ix;
    int y = sy + 4; if (y >= H) y -= H;
    int x = sx + 4; if (x >= W) x -= W;

    for (int idx = tid; idx < 64*32; idx += 64) {
        int j = idx >> 5, c = idx & 31;
        int jy = j >> 3, jx = j & 7;
        int yy = wh*8 + jy + 4; if (yy >= H) yy -= H;
        int xx = ww*8 + jx + 4; if (xx >= W) xx -= W;
        const float* p = feat + ((size_t)(bb*H + yy)*W + xx)*96;
        sK[j][c] = p[32 + c];
        sV[j][c] = p[64 + c];
    }
    for (int idx = tid; idx < 225; idx += 64) sPos[idx] = pos[idx];

    float q[32];
    {
        const float* fp = feat + ((size_t)(bb*H + y)*W + x)*96;
        #pragma unroll
        for (int c = 0; c < 32; c += 4) {
            float4 v = *(const float4*)(fp + c);
            q[c] = v.x; q[c+1] = v.y; q[c+2] = v.z; q[c+3] = v.w;
        }
    }
    __syncthreads();

    const bool mR = (wh == NWIN-1);
    const bool mC = (ww == NWIN-1);
    const float scale = 0.35355339059327373f;
    const int posOff = (7 - iy)*15 + (7 - ix);

    #pragma unroll 1
    for (int h = 0; h < 4; h++) {
        float lg[64];
        float mx = -1e30f;
        #pragma unroll
        for (int j = 0; j < 64; j++) {
            const int jy = j >> 3, jx = j & 7;
            float d = 0.f;
            #pragma unroll
            for (int dd = 0; dd < 8; dd++)
                d = fmaf(q[h*8 + dd], sK[j][h*8 + dd], d);
            float l = d*scale + sPos[jy*15 + jx + posOff];
            bool msk = (mR && ((iy >= 4) != (jy >= 4))) ||
                       (mC && ((ix >= 4) != (jx >= 4)));
            l = msk ? -1e30f : l;
            lg[j] = l;
            mx = fmaxf(mx, l);
        }
        float s = 0.f;
        #pragma unroll
        for (int j = 0; j < 64; j++) {
            float e = __expf(lg[j] - mx);
            lg[j] = e;
            s += e;
        }
        const float inv = 1.f / s;
        float oh[8];
        #pragma unroll
        for (int dd = 0; dd < 8; dd++) oh[dd] = 0.f;
        #pragma unroll
        for (int j = 0; j < 64; j++) {
            float p = lg[j];
            #pragma unroll
            for (int dd = 0; dd < 8; dd++)
                oh[dd] = fmaf(p, sV[j][h*8 + dd], oh[dd]);
        }
        #pragma unroll
        for (int dd = 0; dd < 8; dd++)
            aout[((size_t)(bb*32 + h*8 + dd)*H + sy)*W + sx] = oh[dd]*inv;
    }
}

// =====================================================================
// output conv (32->3) + roll(+4,+4) + residual
// =====================================================================
#define TXO 16
#define TYO 8
#define NTO (TXO*TYO)
__global__ __launch_bounds__(NTO)
void conv_out_k(const float* __restrict__ in, const float* __restrict__ wt,
                const float* __restrict__ bias, const float* __restrict__ xin,
                float* __restrict__ out)
{
    constexpr int CIN = 32, COUT = 3, CHUNK = 16;
    __shared__ float sInb[CHUNK][TYO+2][TXO+2];
    __shared__ float sWb[COUT][CHUNK][9];

    const int bx = blockIdx.x * TXO, by = blockIdx.y * TYO, bb = blockIdx.z;
    const int tid = threadIdx.x;
    const int lx = tid % TXO, ly = tid / TXO;

    float acc[COUT];
    #pragma unroll
    for (int co = 0; co < COUT; co++) acc[co] = __ldg(&bias[co]);

    for (int c0 = 0; c0 < CIN; c0 += CHUNK) {
        __syncthreads();
        for (int idx = tid; idx < COUT*CHUNK*9; idx += NTO) {
            int co = idx / (CHUNK*9);
            int r  = idx - co*(CHUNK*9);
            int ci = r / 9;
            int t  = r - ci*9;
            sWb[co][ci][t] = wt[(co*CIN + c0 + ci)*9 + t];
        }
        {
            const int ty = tid >> 5, tx = tid & 31;
            for (int ci = 0; ci < CHUNK; ci++)
                for (int yy = ty; yy < TYO+2; yy += 4)
                    for (int xx = tx; xx < TXO+2; xx += 32) {
                        int gy = by + yy - 1, gx = bx + xx - 1;
                        float v = 0.f;
                        if ((unsigned)gy < (unsigned)H && (unsigned)gx < (unsigned)W)
                            v = in[((size_t)(bb*CIN + c0 + ci)*H + gy)*W + gx];
                        sInb[ci][yy][xx] = v;
                    }
        }
        __syncthreads();

        #pragma unroll 2
        for (int ci = 0; ci < CHUNK; ci++) {
            float r00 = sInb[ci][ly+0][lx+0], r01 = sInb[ci][ly+0][lx+1], r02 = sInb[ci][ly+0][lx+2];
            float r10 = sInb[ci][ly+1][lx+0], r11 = sInb[ci][ly+1][lx+1], r12 = sInb[ci][ly+1][lx+2];
            float r20 = sInb[ci][ly+2][lx+0], r21 = sInb[ci][ly+2][lx+1], r22 = sInb[ci][ly+2][lx+2];
            #pragma unroll
            for (int co = 0; co < COUT; co++) {
                const float* wp = &sWb[co][ci][0];
                float a = acc[co];
                a = fmaf(r00, wp[0], a);
                a = fmaf(r01, wp[1], a);
                a = fmaf(r02, wp[2], a);
                a = fmaf(r10, wp[3], a);
                a = fmaf(r11, wp[4], a);
                a = fmaf(r12, wp[5], a);
                a = fmaf(r20, wp[6], a);
                a = fmaf(r21, wp[7], a);
                a = fmaf(r22, wp[8], a);
                acc[co] = a;
            }
        }
    }

    const int gy = by + ly, gx = bx + lx;
    int oy = gy + 4; if (oy >= H) oy -= H;
    int ox = gx + 4; if (ox >= W) ox -= W;
    #pragma unroll
    for (int co = 0; co < COUT; co++) {
        size_t idx = ((size_t)(bb*COUT + co)*H + oy)*W + ox;
        out[idx] = xin[idx] + acc[co];
    }
}

// ---------------- launcher ----------------
extern "C" void kernel_launch(void* const* d_in, const int* in_sizes, int n_in,
                              void* d_out, int out_size)
{
    (void)in_sizes; (void)n_in; (void)out_size;
    const float* x   = (const float*)d_in[0];
    const float* wo  = (const float*)d_in[19];
    const float* bo  = (const float*)d_in[20];
    const float* pos = (const float*)d_in[21];
    float* out = (float*)d_out;

    float *h1, *h2, *feat, *aout, *bf1, *bf2, *bf3;
    cudaGetSymbolAddress((void**)&h1,   g_h1);
    cudaGetSymbolAddress((void**)&h2,   g_h2);
    cudaGetSymbolAddress((void**)&feat, g_feat);
    cudaGetSymbolAddress((void**)&aout, g_aout);
    cudaGetSymbolAddress((void**)&bf1,  g_bf1);
    cudaGetSymbolAddress((void**)&bf2,  g_bf2);
    cudaGetSymbolAddress((void**)&bf3,  g_bf3);

    // conv1: CHK=8 PAD=12 KSTEPS=1 NCHUNK=1 NGRP=8 CIN=3 OSTR=64
    // conv2: CHK=32 PAD=36 KSTEPS=4 NCHUNK=2 NGRP=4 CIN=64 OSTR=32
    // conv3: CHK=32 PAD=36 KSTEPS=4 NCHUNK=1 NGRP=4 CIN=32 OSTR=96
    constexpr int SM1 = 4*130*12*4;
    constexpr int SM23 = 4*130*36*4;
    cudaFuncSetAttribute((const void*)gemm_conv_k<32,36,4,2,4,64,32,true,true,false>,
                         cudaFuncAttributeMaxDynamicSharedMemorySize, SM23);
    cudaFuncSetAttribute((const void*)gemm_conv_k<32,36,4,1,4,32,96,false,false,false>,
                         cudaFuncAttributeMaxDynamicSharedMemorySize, SM23);

    // B-fragment prep (3 branches each)
    prep_b_k<8, 1, 1, 8, 3 ><<<dim3(18, 3), 256>>>(
        (const float*)d_in[1], (const float*)d_in[7],  (const float*)d_in[13], bf1);
    prep_b_k<32,4, 2, 4, 64><<<dim3(72, 3), 256>>>(
        (const float*)d_in[3], (const float*)d_in[9],  (const float*)d_in[15], bf2);
    prep_b_k<32,4, 1, 4, 32><<<dim3(36, 3), 256>>>(
        (const float*)d_in[5], (const float*)d_in[11], (const float*)d_in[17], bf3);

    dim3 gg(W/128, H/2, BATCH);
    for (int br = 0; br < 3; br++) {
        const float* b1 = (const float*)d_in[2 + 6*br];
        const float* b2 = (const float*)d_in[4 + 6*br];
        const float* b3 = (const float*)d_in[6 + 6*br];
        gemm_conv_k<8, 12,1,1,8,3, 64,true, true, true ><<<gg, 256, SM1 >>>(x,  bf1 + br*4608,  b1, h1, 0);
        gemm_conv_k<32,36,4,2,4,64,32,true, true, false><<<gg, 256, SM23>>>(h1, bf2 + br*18432, b2, h2, 0);
        gemm_conv_k<32,36,4,1,4,32,96,false,false,false><<<gg, 256, SM23>>>(h2, bf3 + br*9216,  b3, feat, br*32);
    }
    attn_k<<<dim3(NWIN*NWIN, BATCH), 64>>>(feat, pos, aout);
    conv_out_k<<<dim3(W/TXO, H/TYO, BATCH), NTO>>>(aout, wo, bo, x, out);
}